// round 12
// baseline (speedup 1.0000x reference)
#include <cuda_runtime.h>
#include <cstdint>
#include <cstddef>

// Problem constants (B=4, H=8, N=2048, D=64, c=1)
#define BH   32
#define NSEQ 2048
#define DDIM 64
#define TILE_M 128
#define TILE_N 64

// ---------------------------------------------------------------------------
// Precomputed norms (allocation-free: __device__ globals), interleaved pairs:
//  g_qn2[i] = (||q_i||^2, 2/max(1-||q_i||^2, 1e-3))
//  g_kn2[i] = (||k_i||^2, 1/max(1-||k_i||^2, 1e-3))
// ---------------------------------------------------------------------------
__device__ float2 g_qn2[BH * NSEQ];
__device__ float2 g_kn2[BH * NSEQ];

__global__ void norm_kernel(const float* __restrict__ q, const float* __restrict__ k) {
    int i = blockIdx.x * blockDim.x + threadIdx.x;   // 0 .. BH*NSEQ-1
    const float4* qp = (const float4*)(q + (size_t)i * DDIM);
    const float4* kp = (const float4*)(k + (size_t)i * DDIM);
    float sq = 0.f, sk = 0.f;
    #pragma unroll
    for (int j = 0; j < 16; ++j) {
        float4 a = qp[j];
        sq = fmaf(a.x, a.x, fmaf(a.y, a.y, fmaf(a.z, a.z, fmaf(a.w, a.w, sq))));
        float4 b = kp[j];
        sk = fmaf(b.x, b.x, fmaf(b.y, b.y, fmaf(b.z, b.z, fmaf(b.w, b.w, sk))));
    }
    g_qn2[i] = make_float2(sq, 2.f / fmaxf(1.f - sq, 1e-3f));
    g_kn2[i] = make_float2(sk, 1.f / fmaxf(1.f - sk, 1e-3f));
}

// ---------------------------------------------------------------------------
// Helpers
// ---------------------------------------------------------------------------
__device__ __forceinline__ uint32_t smem_u32(const void* p) {
    uint32_t a;
    asm("{ .reg .u64 t; cvta.to.shared.u64 t, %1; cvt.u32.u64 %0, t; }" : "=r"(a) : "l"(p));
    return a;
}
// Pack two fp32 into bf16x2 (lo = first arg = lower k index).
__device__ __forceinline__ uint32_t pack_bf16(float lo, float hi) {
    uint32_t r;
    asm("cvt.rn.bf16x2.f32 %0, %1, %2;" : "=r"(r) : "f"(hi), "f"(lo));
    return r;
}
__device__ __forceinline__ void ldsm_x4(uint32_t* r, uint32_t addr) {
    asm volatile("ldmatrix.sync.aligned.m8n8.x4.shared.b16 {%0,%1,%2,%3}, [%4];"
                 : "=r"(r[0]), "=r"(r[1]), "=r"(r[2]), "=r"(r[3]) : "r"(addr));
}
__device__ __forceinline__ void mma_bf16_16x8x16(float* d, const uint32_t* a, const uint32_t* b) {
    asm volatile(
        "mma.sync.aligned.m16n8k16.row.col.f32.bf16.bf16.f32 "
        "{%0,%1,%2,%3}, {%4,%5,%6,%7}, {%8,%9}, {%0,%1,%2,%3};"
        : "+f"(d[0]), "+f"(d[1]), "+f"(d[2]), "+f"(d[3])
        : "r"(a[0]), "r"(a[1]), "r"(a[2]), "r"(a[3]), "r"(b[0]), "r"(b[1]));
}

// acosh(z) with z = 1 + max(diff,0)*rr, computed as log(z + sqrt(z^2-1)).
// z >= 1 always (fma with +1); z==1 -> u2 = fma(1,1,-1) = 0 exactly -> d = 0.
__device__ __forceinline__ float hyp_dist(float s, float qnkn, float rr) {
    float diff = fmaf(-2.f, s, qnkn);
    float z = fmaf(fmaxf(diff, 0.f), rr, 1.f);
    float u2 = fmaf(z, z, -1.f);
    float u;
    asm("sqrt.approx.f32 %0, %1;" : "=f"(u) : "f"(u2));
    return __logf(z + u);
}

// ---------------------------------------------------------------------------
// Main kernel: 128x64 output tile per CTA, 128 threads = 4 warps (2M x 2N),
// warp tile 64x32 = 4x4 m16n8k16 (bf16 in, fp32 accum). Target 6 CTAs/SM
// (regs <= 84: cn column norms re-read from smem inside the epilogue loop
// instead of being held in registers across the barrier).
//
// Tiles stored ROW-MAJOR bf16 (row pitch 128B = 8 x 16B chunks), swizzled:
//   byte addr = row*128 + ((chunk ^ (row&7)) << 4) + sub8
// Producer: float4 -> 2 bf16x2 -> one STS.64, conflict-free.
// Mainloop: per k-step load B (2 ldmatrix.x4), then per mi: 1 ldmatrix.x4 A
// followed by its 4 MMAs (minimal live registers).
//
// Staged epilogue: hyp_dist in-register, stage fp32 in smem (float2 slot
// c2 ^ (g<<2)), then coalesced row copy LDS.128 -> STG.128.
// qn2s/cn2s live OUTSIDE the stage region, so they remain valid after the
// stage reuse barrier.
//
// smem (static 34KB): A [0:16K), B [16K:24K), stage [0:32K) reuse,
// qn2s [32K:33K), cn2s [33K:33.5K)
// ---------------------------------------------------------------------------
__global__ __launch_bounds__(128, 6)
void hyp_kernel(const float* __restrict__ q,
                const float* __restrict__ k,
                float* __restrict__ out) {
    __shared__ __align__(16) char smem[34816];
    char*   afrag = smem;                        // 128 x 128B
    char*   bfrag = smem + 16384;                // 64 x 128B
    float2* stage = (float2*)smem;               // 128 x 32 float2
    float2* qn2s  = (float2*)(smem + 32768);     // 128
    float2* cn2s  = (float2*)(smem + 33792);     // 64

    const int tid  = threadIdx.x;
    const int lane = tid & 31;
    const int wid  = tid >> 5;
    const int wm   = wid >> 1;   // 0..1  (M half)
    const int wn   = wid & 1;    // 0..1  (N half)
    const int bn = blockIdx.x;   // N tile (0..31)
    const int bm = blockIdx.y;   // M tile (0..15)
    const int bz = blockIdx.z;   // batch

    // ---- Producer: LDG.128 -> pack bf16 -> STS.64 row-major swizzled
    {
        const float4* qb = (const float4*)(q + ((size_t)bz * NSEQ + bm * TILE_M) * DDIM);
        const float4* kb = (const float4*)(k + ((size_t)bz * NSEQ + bn * TILE_N) * DDIM);
        const int j  = tid & 15;       // float4-col (bf16 cols 4j..4j+3)
        const int r0 = tid >> 4;       // 0..7
        const int off = (((j >> 1) ^ r0) << 4) + ((j & 1) << 3);
        #pragma unroll
        for (int i = 0; i < 16; ++i) {            // A rows r0 + 8i
            float4 v = qb[tid + 128 * i];
            uint2 w = make_uint2(pack_bf16(v.x, v.y), pack_bf16(v.z, v.w));
            *(uint2*)(afrag + (r0 + 8 * i) * 128 + off) = w;
        }
        #pragma unroll
        for (int i = 0; i < 8; ++i) {             // B rows r0 + 8i
            float4 v = kb[tid + 128 * i];
            uint2 w = make_uint2(pack_bf16(v.x, v.y), pack_bf16(v.z, v.w));
            *(uint2*)(bfrag + (r0 + 8 * i) * 128 + off) = w;
        }
    }
    // ---- Norm pairs -> smem
    qn2s[tid] = g_qn2[bz * NSEQ + bm * TILE_M + tid];
    if (tid < 64) cn2s[tid] = g_kn2[bz * NSEQ + bn * TILE_N + tid];

    __syncthreads();

    // ---- Main MMA loop: 4 k-steps of k16, ldmatrix operand loads
    float acc[4][4][4];
    #pragma unroll
    for (int mi = 0; mi < 4; ++mi)
        #pragma unroll
        for (int ni = 0; ni < 4; ++ni)
            #pragma unroll
            for (int r = 0; r < 4; ++r) acc[mi][ni][r] = 0.f;

    // Per-lane ldmatrix row addresses (chunk offset added per step).
    const int grp = lane >> 3;        // 0..3
    const int rl  = lane & 7;
    // A: matrices {a0,a1,a2,a3}: row sub = (grp&1)*8 + rl, chunk bit = grp>>1
    const uint32_t a_rowaddr = smem_u32(afrag) +
        (wm * 64 + ((grp & 1) << 3) + rl) * 128;
    const int abit = grp >> 1;
    // B: matrices {b0(ni),b1(ni),b0(ni+1),b1(ni+1)}: row sub = (grp>>1)*8 + rl,
    // chunk bit = grp&1
    const uint32_t b_rowaddr = smem_u32(bfrag) +
        (wn * 32 + ((grp >> 1) << 3) + rl) * 128;
    const int bbit = grp & 1;

    #pragma unroll
    for (int s = 0; s < 4; ++s) {
        const uint32_t aoff = (uint32_t)(((2 * s + abit) ^ rl) << 4);
        const uint32_t boff = (uint32_t)(((2 * s + bbit) ^ rl) << 4);
        uint32_t Bf[4][2];
        ldsm_x4(&Bf[0][0], b_rowaddr + boff);                  // ni 0,1
        ldsm_x4(&Bf[2][0], b_rowaddr + (16 * 128) + boff);     // ni 2,3
        #pragma unroll
        for (int mi = 0; mi < 4; ++mi) {
            uint32_t A[4];
            ldsm_x4(A, a_rowaddr + mi * (16 * 128) + aoff);
            #pragma unroll
            for (int ni = 0; ni < 4; ++ni)
                mma_bf16_16x8x16(acc[mi][ni], A, Bf[ni]);
        }
    }

    // ---- Epilogue part 1: hyp_dist in-register, stage fp32 in smem
    const int g  = lane >> 2;
    const int t4 = lane & 3;

    __syncthreads();   // all fragment reads done; frag region becomes stage
                       // (qn2s/cn2s are outside the stage region, still valid)

    #pragma unroll
    for (int mi = 0; mi < 4; ++mi) {
        int r0 = wm * 64 + mi * 16 + g;
        float2 qa = qn2s[r0];
        float2 qc = qn2s[r0 + 8];
        #pragma unroll
        for (int ni = 0; ni < 4; ++ni) {
            float4 cnl = *(const float4*)&cn2s[wn * 32 + ni * 8 + t4 * 2];
            int c2 = (wn * 16 + ni * 4 + t4) ^ (g << 2);   // swizzled float2 slot
            float2 v0, v1;
            v0.x = hyp_dist(acc[mi][ni][0], qa.x + cnl.x, qa.y * cnl.y);
            v0.y = hyp_dist(acc[mi][ni][1], qa.x + cnl.z, qa.y * cnl.w);
            v1.x = hyp_dist(acc[mi][ni][2], qc.x + cnl.x, qc.y * cnl.y);
            v1.y = hyp_dist(acc[mi][ni][3], qc.x + cnl.z, qc.y * cnl.w);
            stage[r0 * 32 + c2]       = v0;
            stage[(r0 + 8) * 32 + c2] = v1;
        }
    }

    __syncthreads();

    // ---- Epilogue part 2: coalesced row copy (2 rows per warp instruction)
    float* ob = out + ((size_t)bz << 22) + (size_t)(bm * TILE_M) * NSEQ + bn * TILE_N;
    const float4* stage4 = (const float4*)smem;   // 128 rows x 16 float4
    const int f = lane & 15;
    #pragma unroll
    for (int ii = 0; ii < 16; ++ii) {
        int row = wid * 32 + ii * 2 + (lane >> 4);
        float4 v = stage4[row * 16 + (f ^ (((row & 7)) << 1))];
        *(float4*)(ob + (size_t)row * NSEQ + 4 * f) = v;
    }
}

// ---------------------------------------------------------------------------
// Launch
// ---------------------------------------------------------------------------
extern "C" void kernel_launch(void* const* d_in, const int* in_sizes, int n_in,
                              void* d_out, int out_size) {
    const float* q = (const float*)d_in[0];
    const float* k = (const float*)d_in[1];
    float* out = (float*)d_out;

    norm_kernel<<<(BH * NSEQ) / 256, 256>>>(q, k);

    dim3 grid(NSEQ / TILE_N, NSEQ / TILE_M, BH);
    hyp_kernel<<<grid, 128>>>(q, k, out);
}

// round 13
// speedup vs baseline: 1.2818x; 1.2818x over previous
#include <cuda_runtime.h>
#include <cuda_bf16.h>
#include <cstdint>
#include <cstddef>

// Problem constants (B=4, H=8, N=2048, D=64, c=1)
#define BH   32
#define NSEQ 2048
#define DDIM 64
#define TILE_M 128
#define TILE_N 64

// ---------------------------------------------------------------------------
// Prepared operands (device globals; allocation-free rule).
// Each row i: 80 bf16 = 10 uint4 chunks.
//  qprep: [-2*rq*q_d (64) | rqqn_hi rqqn_lo rqqn_hi rq_hi rq_lo rq_hi | 0 x10]
//  kprep: [ rk*k_d  (64) | rk_hi  rk_hi  rk_lo  rkkn_hi rkkn_hi rkkn_lo | 0 x10]
// with rq = 2/max(1-qn,1e-3), rk = 1/max(1-kn,1e-3). The augmented dot then
// equals z-1 = rq*rk*(qn+kn-2*q.k) exactly up to bf16 lo*lo cross terms.
// ---------------------------------------------------------------------------
__device__ uint4 g_qprep[BH * NSEQ * 10];
__device__ uint4 g_kprep[BH * NSEQ * 10];

// Pack two fp32 into bf16x2 (lo arg = lower index / low half).
__device__ __forceinline__ uint32_t pack_bf16(float lo, float hi) {
    uint32_t r;
    asm("cvt.rn.bf16x2.f32 %0, %1, %2;" : "=r"(r) : "f"(hi), "f"(lo));
    return r;
}

__global__ void prep_kernel(const float* __restrict__ q, const float* __restrict__ k) {
    int i = blockIdx.x * blockDim.x + threadIdx.x;   // row 0..BH*NSEQ-1
    const float4* qr = (const float4*)(q + (size_t)i * DDIM);
    const float4* kr = (const float4*)(k + (size_t)i * DDIM);

    float4 qv[16], kv[16];
    float qn = 0.f, kn = 0.f;
    #pragma unroll
    for (int j = 0; j < 16; ++j) {
        qv[j] = qr[j];
        qn = fmaf(qv[j].x, qv[j].x, fmaf(qv[j].y, qv[j].y,
             fmaf(qv[j].z, qv[j].z, fmaf(qv[j].w, qv[j].w, qn))));
        kv[j] = kr[j];
        kn = fmaf(kv[j].x, kv[j].x, fmaf(kv[j].y, kv[j].y,
             fmaf(kv[j].z, kv[j].z, fmaf(kv[j].w, kv[j].w, kn))));
    }
    float rq = 2.f / fmaxf(1.f - qn, 1e-3f);
    float rk = 1.f / fmaxf(1.f - kn, 1e-3f);

    // main dims
    uint4* qo = g_qprep + (size_t)i * 10;
    uint4* ko = g_kprep + (size_t)i * 10;
    float mq = -2.f * rq;
    #pragma unroll
    for (int c = 0; c < 8; ++c) {
        float4 a = qv[2 * c], b = qv[2 * c + 1];
        qo[c] = make_uint4(pack_bf16(mq * a.x, mq * a.y), pack_bf16(mq * a.z, mq * a.w),
                           pack_bf16(mq * b.x, mq * b.y), pack_bf16(mq * b.z, mq * b.w));
        float4 e = kv[2 * c], f = kv[2 * c + 1];
        ko[c] = make_uint4(pack_bf16(rk * e.x, rk * e.y), pack_bf16(rk * e.z, rk * e.w),
                           pack_bf16(rk * f.x, rk * f.y), pack_bf16(rk * f.z, rk * f.w));
    }
    // augmented dims with hi/lo splits
    float rqqn = rq * qn;
    float h1 = __bfloat162float(__float2bfloat16(rqqn)), l1 = rqqn - h1;
    float h2 = __bfloat162float(__float2bfloat16(rq)),   l2 = rq - h2;
    qo[8] = make_uint4(pack_bf16(h1, l1), pack_bf16(h1, h2), pack_bf16(l2, h2), 0u);
    qo[9] = make_uint4(0u, 0u, 0u, 0u);

    float rkkn = rk * kn;
    float h3 = __bfloat162float(__float2bfloat16(rk)),   l3 = rk - h3;
    float h4 = __bfloat162float(__float2bfloat16(rkkn)), l4 = rkkn - h4;
    ko[8] = make_uint4(pack_bf16(h3, h3), pack_bf16(l3, h4), pack_bf16(h4, l4), 0u);
    ko[9] = make_uint4(0u, 0u, 0u, 0u);
}

// ---------------------------------------------------------------------------
// Helpers
// ---------------------------------------------------------------------------
__device__ __forceinline__ uint32_t smem_u32(const void* p) {
    uint32_t a;
    asm("{ .reg .u64 t; cvta.to.shared.u64 t, %1; cvt.u32.u64 %0, t; }" : "=r"(a) : "l"(p));
    return a;
}
__device__ __forceinline__ void ldsm_x4(uint32_t* r, uint32_t addr) {
    asm volatile("ldmatrix.sync.aligned.m8n8.x4.shared.b16 {%0,%1,%2,%3}, [%4];"
                 : "=r"(r[0]), "=r"(r[1]), "=r"(r[2]), "=r"(r[3]) : "r"(addr));
}
__device__ __forceinline__ void mma_bf16_16x8x16(float* d, const uint32_t* a, const uint32_t* b) {
    asm volatile(
        "mma.sync.aligned.m16n8k16.row.col.f32.bf16.bf16.f32 "
        "{%0,%1,%2,%3}, {%4,%5,%6,%7}, {%8,%9}, {%0,%1,%2,%3};"
        : "+f"(d[0]), "+f"(d[1]), "+f"(d[2]), "+f"(d[3])
        : "r"(a[0]), "r"(a[1]), "r"(a[2]), "r"(a[3]), "r"(b[0]), "r"(b[1]));
}

// acc = z-1 (>= 0 up to rounding). d = acosh(z) = log(z + sqrt(z^2-1)).
__device__ __forceinline__ float hyp_from_acc(float acc) {
    float z = 1.f + fmaxf(acc, 0.f);
    float u2 = fmaf(z, z, -1.f);
    float u;
    asm("sqrt.approx.f32 %0, %1;" : "=f"(u) : "f"(u2));
    return __logf(z + u);
}

// ---------------------------------------------------------------------------
// Main kernel: 128x64 tile per CTA, 128 threads = 4 warps (2M x 2N),
// warp tile 64x32, 5 k-steps of m16n8k16 (K=80 augmented). 5 CTAs/SM.
//
// smem (static 32KB):
//   afrag [0:16K)      A main 128 rows x 128B, swizzle chunk^(row&7)
//   aex   [16K:20K)    A aug: 8 tiles x (2 chunks x 16 rows x 16B) chunk-major
//   bfrag [20K:28K)    B main 64 rows x 128B, swizzled
//   bex   [28K:30K)    B aug: 4 tiles, same mini-layout
//   stage [0:32K)      reuse after mainloop: final fp32, then coalesced copy
// ---------------------------------------------------------------------------
__global__ __launch_bounds__(128, 5)
void hyp_kernel(float* __restrict__ out) {
    __shared__ __align__(16) char smem[32768];
    char* afrag = smem;
    char* aex   = smem + 16384;
    char* bfrag = smem + 20480;
    char* bex   = smem + 28672;
    float2* stage = (float2*)smem;

    const int tid  = threadIdx.x;
    const int lane = tid & 31;
    const int wid  = tid >> 5;
    const int wm   = wid >> 1;   // 0..1  (M half)
    const int wn   = wid & 1;    // 0..1  (N half)
    const int bn = blockIdx.x;   // N tile (0..31)
    const int bm = blockIdx.y;   // M tile (0..15)
    const int bz = blockIdx.z;   // batch

    // ---- Producer: pure bf16 uint4 copy from prepared rows
    {
        const uint4* qp = g_qprep + (size_t)(bz * NSEQ + bm * TILE_M) * 10;
        const uint4* kp = g_kprep + (size_t)(bz * NSEQ + bn * TILE_N) * 10;
        const int j = tid & 7;        // 16B chunk 0..7
        const int r = tid >> 3;       // 0..15
        const int off = ((j ^ (r & 7)) << 4);
        #pragma unroll
        for (int i = 0; i < 8; ++i) {             // A main rows r + 16i
            int row = r + 16 * i;
            *(uint4*)(afrag + row * 128 + off) = qp[row * 10 + j];
        }
        #pragma unroll
        for (int i = 0; i < 4; ++i) {             // B main rows r + 16i
            int row = r + 16 * i;
            *(uint4*)(bfrag + row * 128 + off) = kp[row * 10 + j];
        }
        // A aug: thread = row; tile(row>>4)*512 + chunk*256 + (row&15)*16
        {
            int base = ((tid >> 4) << 9) + ((tid & 15) << 4);
            *(uint4*)(aex + base)       = qp[tid * 10 + 8];
            *(uint4*)(aex + base + 256) = qp[tid * 10 + 9];
        }
        if (tid < 64) {
            int base = ((tid >> 4) << 9) + ((tid & 15) << 4);
            *(uint4*)(bex + base)       = kp[tid * 10 + 8];
            *(uint4*)(bex + base + 256) = kp[tid * 10 + 9];
        }
    }

    __syncthreads();

    // ---- Main MMA loop: 4 main k-steps + 1 augmented step
    float acc[4][4][4];
    #pragma unroll
    for (int mi = 0; mi < 4; ++mi)
        #pragma unroll
        for (int ni = 0; ni < 4; ++ni)
            #pragma unroll
            for (int r = 0; r < 4; ++r) acc[mi][ni][r] = 0.f;

    const int grp = lane >> 3;
    const int rl  = lane & 7;
    const uint32_t a_rowaddr = smem_u32(afrag) +
        (wm * 64 + ((grp & 1) << 3) + rl) * 128;
    const int abit = grp >> 1;
    const uint32_t b_rowaddr = smem_u32(bfrag) +
        (wn * 32 + ((grp >> 1) << 3) + rl) * 128;
    const int bbit = grp & 1;

    #pragma unroll
    for (int s = 0; s < 4; ++s) {
        const uint32_t aoff = (uint32_t)(((2 * s + abit) ^ rl) << 4);
        const uint32_t boff = (uint32_t)(((2 * s + bbit) ^ rl) << 4);
        uint32_t Bf[4][2];
        ldsm_x4(&Bf[0][0], b_rowaddr + boff);                  // ni 0,1
        ldsm_x4(&Bf[2][0], b_rowaddr + (16 * 128) + boff);     // ni 2,3
        #pragma unroll
        for (int mi = 0; mi < 4; ++mi) {
            uint32_t A[4];
            ldsm_x4(A, a_rowaddr + mi * (16 * 128) + aoff);
            #pragma unroll
            for (int ni = 0; ni < 4; ++ni)
                mma_bf16_16x8x16(acc[mi][ni], A, Bf[ni]);
        }
    }
    // augmented k-step (K 64..79), chunk-major mini-layout
    {
        const uint32_t a4 = smem_u32(aex) + ((wm * 4) << 9) + (abit << 8) +
                            ((((grp & 1) << 3) + rl) << 4);
        const uint32_t b4 = smem_u32(bex) + ((wn * 2) << 9) + (bbit << 8) +
                            ((((grp >> 1) << 3) + rl) << 4);
        uint32_t Bf[4][2];
        ldsm_x4(&Bf[0][0], b4);          // ni 0,1
        ldsm_x4(&Bf[2][0], b4 + 512);    // ni 2,3
        #pragma unroll
        for (int mi = 0; mi < 4; ++mi) {
            uint32_t A[4];
            ldsm_x4(A, a4 + mi * 512);
            #pragma unroll
            for (int ni = 0; ni < 4; ++ni)
                mma_bf16_16x8x16(acc[mi][ni], A, Bf[ni]);
        }
    }

    // ---- Epilogue part 1: acosh in-register, stage fp32 in smem
    const int g  = lane >> 2;
    const int t4 = lane & 3;

    __syncthreads();   // frag regions become the stage

    #pragma unroll
    for (int mi = 0; mi < 4; ++mi) {
        int r0 = wm * 64 + mi * 16 + g;
        #pragma unroll
        for (int ni = 0; ni < 4; ++ni) {
            int c2 = (wn * 16 + ni * 4 + t4) ^ (g << 2);   // swizzled float2 slot
            float2 v0, v1;
            v0.x = hyp_from_acc(acc[mi][ni][0]);
            v0.y = hyp_from_acc(acc[mi][ni][1]);
            v1.x = hyp_from_acc(acc[mi][ni][2]);
            v1.y = hyp_from_acc(acc[mi][ni][3]);
            stage[r0 * 32 + c2]       = v0;
            stage[(r0 + 8) * 32 + c2] = v1;
        }
    }

    __syncthreads();

    // ---- Epilogue part 2: coalesced row copy (2 rows per warp instruction)
    float* ob = out + ((size_t)bz << 22) + (size_t)(bm * TILE_M) * NSEQ + bn * TILE_N;
    const float4* stage4 = (const float4*)smem;   // 128 rows x 16 float4
    const int f = lane & 15;
    #pragma unroll
    for (int ii = 0; ii < 16; ++ii) {
        int row = wid * 32 + ii * 2 + (lane >> 4);
        float4 v = stage4[row * 16 + (f ^ (((row & 7)) << 1))];
        *(float4*)(ob + (size_t)row * NSEQ + 4 * f) = v;
    }
}

// ---------------------------------------------------------------------------
// Launch
// ---------------------------------------------------------------------------
extern "C" void kernel_launch(void* const* d_in, const int* in_sizes, int n_in,
                              void* d_out, int out_size) {
    const float* q = (const float*)d_in[0];
    const float* k = (const float*)d_in[1];
    float* out = (float*)d_out;

    prep_kernel<<<(BH * NSEQ) / 256, 256>>>(q, k);

    dim3 grid(NSEQ / TILE_N, NSEQ / TILE_M, BH);
    hyp_kernel<<<grid, 128>>>(out);
}

// round 15
// speedup vs baseline: 1.3393x; 1.0448x over previous
#include <cuda_runtime.h>
#include <cuda_bf16.h>
#include <cstdint>
#include <cstddef>

// Problem constants (B=4, H=8, N=2048, D=64, c=1)
#define BH   32
#define NSEQ 2048
#define DDIM 64
#define TILE_M 128
#define TILE_N 64

// ---------------------------------------------------------------------------
// Prepared operands (device globals; allocation-free rule).
// Each row i: 80 bf16 = 10 uint4 chunks.
//  qprep: [-2*rq*q_d (64) | rqqn_hi rqqn_lo rqqn_hi rq_hi rq_lo rq_hi | 0 x10]
//  kprep: [ rk*k_d  (64) | rk_hi  rk_hi  rk_lo  rkkn_hi rkkn_hi rkkn_lo | 0 x10]
// with rq = 2/max(1-qn,1e-3), rk = 1/max(1-kn,1e-3). The augmented dot then
// equals z-1 = rq*rk*(qn+kn-2*q.k) exactly up to bf16 lo*lo cross terms.
// ---------------------------------------------------------------------------
__device__ uint4 g_qprep[BH * NSEQ * 10];
__device__ uint4 g_kprep[BH * NSEQ * 10];

// Pack two fp32 into bf16x2 (lo arg = lower index / low half).
__device__ __forceinline__ uint32_t pack_bf16(float lo, float hi) {
    uint32_t r;
    asm("cvt.rn.bf16x2.f32 %0, %1, %2;" : "=r"(r) : "f"(hi), "f"(lo));
    return r;
}

// 4 threads per row: thread quarter h covers dims 16h..16h+15 (float4 j=4h..4h+3,
// output chunks 2h, 2h+1). Quad shfl reduces norms; aug chunks distributed
// one per quad lane.
__global__ void prep_kernel(const float* __restrict__ q, const float* __restrict__ k) {
    int gid = blockIdx.x * blockDim.x + threadIdx.x;   // 0 .. 4*BH*NSEQ-1
    int i = gid >> 2;     // row
    int h = gid & 3;      // quarter

    const float4* qr = (const float4*)(q + (size_t)i * DDIM) + 4 * h;
    const float4* kr = (const float4*)(k + (size_t)i * DDIM) + 4 * h;

    float4 qv[4], kv[4];
    float qn = 0.f, kn = 0.f;
    #pragma unroll
    for (int j = 0; j < 4; ++j) {
        qv[j] = qr[j];
        qn = fmaf(qv[j].x, qv[j].x, fmaf(qv[j].y, qv[j].y,
             fmaf(qv[j].z, qv[j].z, fmaf(qv[j].w, qv[j].w, qn))));
        kv[j] = kr[j];
        kn = fmaf(kv[j].x, kv[j].x, fmaf(kv[j].y, kv[j].y,
             fmaf(kv[j].z, kv[j].z, fmaf(kv[j].w, kv[j].w, kn))));
    }
    // quad reduction (lanes gid, gid^1, gid^2 are the same row's quarters)
    qn += __shfl_xor_sync(0xffffffffu, qn, 1);
    qn += __shfl_xor_sync(0xffffffffu, qn, 2);
    kn += __shfl_xor_sync(0xffffffffu, kn, 1);
    kn += __shfl_xor_sync(0xffffffffu, kn, 2);

    float rq = 2.f / fmaxf(1.f - qn, 1e-3f);
    float rk = 1.f / fmaxf(1.f - kn, 1e-3f);

    // main chunks 2h, 2h+1
    uint4* qo = g_qprep + (size_t)i * 10 + 2 * h;
    uint4* ko = g_kprep + (size_t)i * 10 + 2 * h;
    float mq = -2.f * rq;
    #pragma unroll
    for (int c = 0; c < 2; ++c) {
        float4 a = qv[2 * c], b = qv[2 * c + 1];
        qo[c] = make_uint4(pack_bf16(mq * a.x, mq * a.y), pack_bf16(mq * a.z, mq * a.w),
                           pack_bf16(mq * b.x, mq * b.y), pack_bf16(mq * b.z, mq * b.w));
        float4 e = kv[2 * c], f = kv[2 * c + 1];
        ko[c] = make_uint4(pack_bf16(rk * e.x, rk * e.y), pack_bf16(rk * e.z, rk * e.w),
                           pack_bf16(rk * f.x, rk * f.y), pack_bf16(rk * f.z, rk * f.w));
    }

    // aug chunks: one per quad lane
    if (h == 0) {
        float rqqn = rq * qn;
        float h1 = __bfloat162float(__float2bfloat16(rqqn)), l1 = rqqn - h1;
        float h2 = __bfloat162float(__float2bfloat16(rq)),   l2 = rq - h2;
        g_qprep[(size_t)i * 10 + 8] =
            make_uint4(pack_bf16(h1, l1), pack_bf16(h1, h2), pack_bf16(l2, h2), 0u);
    } else if (h == 1) {
        g_qprep[(size_t)i * 10 + 9] = make_uint4(0u, 0u, 0u, 0u);
    } else if (h == 2) {
        float rkkn = rk * kn;
        float h3 = __bfloat162float(__float2bfloat16(rk)),   l3 = rk - h3;
        float h4 = __bfloat162float(__float2bfloat16(rkkn)), l4 = rkkn - h4;
        g_kprep[(size_t)i * 10 + 8] =
            make_uint4(pack_bf16(h3, h3), pack_bf16(l3, h4), pack_bf16(h4, l4), 0u);
    } else {
        g_kprep[(size_t)i * 10 + 9] = make_uint4(0u, 0u, 0u, 0u);
    }
}

// ---------------------------------------------------------------------------
// Helpers
// ---------------------------------------------------------------------------
__device__ __forceinline__ uint32_t smem_u32(const void* p) {
    uint32_t a;
    asm("{ .reg .u64 t; cvta.to.shared.u64 t, %1; cvt.u32.u64 %0, t; }" : "=r"(a) : "l"(p));
    return a;
}
__device__ __forceinline__ void ldsm_x4(uint32_t* r, uint32_t addr) {
    asm volatile("ldmatrix.sync.aligned.m8n8.x4.shared.b16 {%0,%1,%2,%3}, [%4];"
                 : "=r"(r[0]), "=r"(r[1]), "=r"(r[2]), "=r"(r[3]) : "r"(addr));
}
__device__ __forceinline__ void mma_bf16_16x8x16(float* d, const uint32_t* a, const uint32_t* b) {
    asm volatile(
        "mma.sync.aligned.m16n8k16.row.col.f32.bf16.bf16.f32 "
        "{%0,%1,%2,%3}, {%4,%5,%6,%7}, {%8,%9}, {%0,%1,%2,%3};"
        : "+f"(d[0]), "+f"(d[1]), "+f"(d[2]), "+f"(d[3])
        : "r"(a[0]), "r"(a[1]), "r"(a[2]), "r"(a[3]), "r"(b[0]), "r"(b[1]));
}

// acc = z-1 (>= 0 up to rounding). d = acosh(z) = log(z + sqrt(z^2-1)).
__device__ __forceinline__ float hyp_from_acc(float acc) {
    float z = 1.f + fmaxf(acc, 0.f);
    float u2 = fmaf(z, z, -1.f);
    float u;
    asm("sqrt.approx.f32 %0, %1;" : "=f"(u) : "f"(u2));
    return __logf(z + u);
}

// ---------------------------------------------------------------------------
// Main kernel: 128x64 tile per CTA, 128 threads = 4 warps (2M x 2N),
// warp tile 64x32, 5 k-steps of m16n8k16 (K=80 augmented). 5 CTAs/SM.
//
// smem (static 32KB):
//   afrag [0:16K)      A main 128 rows x 128B, swizzle chunk^(row&7)
//   aex   [16K:20K)    A aug: 8 tiles x (2 chunks x 16 rows x 16B) chunk-major
//   bfrag [20K:28K)    B main 64 rows x 128B, swizzled
//   bex   [28K:30K)    B aug: 4 tiles, same mini-layout
//   stage [0:32K)      reuse after mainloop: final fp32, then coalesced copy
// ---------------------------------------------------------------------------
__global__ __launch_bounds__(128, 5)
void hyp_kernel(float* __restrict__ out) {
    __shared__ __align__(16) char smem[32768];
    char* afrag = smem;
    char* aex   = smem + 16384;
    char* bfrag = smem + 20480;
    char* bex   = smem + 28672;
    float2* stage = (float2*)smem;

    const int tid  = threadIdx.x;
    const int lane = tid & 31;
    const int wid  = tid >> 5;
    const int wm   = wid >> 1;   // 0..1  (M half)
    const int wn   = wid & 1;    // 0..1  (N half)
    const int bn = blockIdx.x;   // N tile (0..31)
    const int bm = blockIdx.y;   // M tile (0..15)
    const int bz = blockIdx.z;   // batch

    // ---- Producer: pure bf16 uint4 copy from prepared rows
    {
        const uint4* qp = g_qprep + (size_t)(bz * NSEQ + bm * TILE_M) * 10;
        const uint4* kp = g_kprep + (size_t)(bz * NSEQ + bn * TILE_N) * 10;
        const int j = tid & 7;        // 16B chunk 0..7
        const int r = tid >> 3;       // 0..15
        const int off = ((j ^ (r & 7)) << 4);
        #pragma unroll
        for (int i = 0; i < 8; ++i) {             // A main rows r + 16i
            int row = r + 16 * i;
            *(uint4*)(afrag + row * 128 + off) = qp[row * 10 + j];
        }
        #pragma unroll
        for (int i = 0; i < 4; ++i) {             // B main rows r + 16i
            int row = r + 16 * i;
            *(uint4*)(bfrag + row * 128 + off) = kp[row * 10 + j];
        }
        // A aug: thread = row; tile(row>>4)*512 + chunk*256 + (row&15)*16
        {
            int base = ((tid >> 4) << 9) + ((tid & 15) << 4);
            *(uint4*)(aex + base)       = qp[tid * 10 + 8];
            *(uint4*)(aex + base + 256) = qp[tid * 10 + 9];
        }
        if (tid < 64) {
            int base = ((tid >> 4) << 9) + ((tid & 15) << 4);
            *(uint4*)(bex + base)       = kp[tid * 10 + 8];
            *(uint4*)(bex + base + 256) = kp[tid * 10 + 9];
        }
    }

    __syncthreads();

    // ---- Main MMA loop: 4 main k-steps + 1 augmented step
    float acc[4][4][4];
    #pragma unroll
    for (int mi = 0; mi < 4; ++mi)
        #pragma unroll
        for (int ni = 0; ni < 4; ++ni)
            #pragma unroll
            for (int r = 0; r < 4; ++r) acc[mi][ni][r] = 0.f;

    const int grp = lane >> 3;
    const int rl  = lane & 7;
    const uint32_t a_rowaddr = smem_u32(afrag) +
        (wm * 64 + ((grp & 1) << 3) + rl) * 128;
    const int abit = grp >> 1;
    const uint32_t b_rowaddr = smem_u32(bfrag) +
        (wn * 32 + ((grp >> 1) << 3) + rl) * 128;
    const int bbit = grp & 1;

    #pragma unroll
    for (int s = 0; s < 4; ++s) {
        const uint32_t aoff = (uint32_t)(((2 * s + abit) ^ rl) << 4);
        const uint32_t boff = (uint32_t)(((2 * s + bbit) ^ rl) << 4);
        uint32_t Bf[4][2];
        ldsm_x4(&Bf[0][0], b_rowaddr + boff);                  // ni 0,1
        ldsm_x4(&Bf[2][0], b_rowaddr + (16 * 128) + boff);     // ni 2,3
        #pragma unroll
        for (int mi = 0; mi < 4; ++mi) {
            uint32_t A[4];
            ldsm_x4(A, a_rowaddr + mi * (16 * 128) + aoff);
            #pragma unroll
            for (int ni = 0; ni < 4; ++ni)
                mma_bf16_16x8x16(acc[mi][ni], A, Bf[ni]);
        }
    }
    // augmented k-step (K 64..79), chunk-major mini-layout
    {
        const uint32_t a4 = smem_u32(aex) + ((wm * 4) << 9) + (abit << 8) +
                            ((((grp & 1) << 3) + rl) << 4);
        const uint32_t b4 = smem_u32(bex) + ((wn * 2) << 9) + (bbit << 8) +
                            ((((grp >> 1) << 3) + rl) << 4);
        uint32_t Bf[4][2];
        ldsm_x4(&Bf[0][0], b4);          // ni 0,1
        ldsm_x4(&Bf[2][0], b4 + 512);    // ni 2,3
        #pragma unroll
        for (int mi = 0; mi < 4; ++mi) {
            uint32_t A[4];
            ldsm_x4(A, a4 + mi * 512);
            #pragma unroll
            for (int ni = 0; ni < 4; ++ni)
                mma_bf16_16x8x16(acc[mi][ni], A, Bf[ni]);
        }
    }

    // ---- Epilogue part 1: acosh in-register, stage fp32 in smem
    const int g  = lane >> 2;
    const int t4 = lane & 3;

    __syncthreads();   // frag regions become the stage

    #pragma unroll
    for (int mi = 0; mi < 4; ++mi) {
        int r0 = wm * 64 + mi * 16 + g;
        #pragma unroll
        for (int ni = 0; ni < 4; ++ni) {
            int c2 = (wn * 16 + ni * 4 + t4) ^ (g << 2);   // swizzled float2 slot
            float2 v0, v1;
            v0.x = hyp_from_acc(acc[mi][ni][0]);
            v0.y = hyp_from_acc(acc[mi][ni][1]);
            v1.x = hyp_from_acc(acc[mi][ni][2]);
            v1.y = hyp_from_acc(acc[mi][ni][3]);
            stage[r0 * 32 + c2]       = v0;
            stage[(r0 + 8) * 32 + c2] = v1;
        }
    }

    __syncthreads();

    // ---- Epilogue part 2: coalesced row copy (2 rows per warp instruction)
    float* ob = out + ((size_t)bz << 22) + (size_t)(bm * TILE_M) * NSEQ + bn * TILE_N;
    const float4* stage4 = (const float4*)smem;   // 128 rows x 16 float4
    const int f = lane & 15;
    #pragma unroll
    for (int ii = 0; ii < 16; ++ii) {
        int row = wid * 32 + ii * 2 + (lane >> 4);
        float4 v = stage4[row * 16 + (f ^ (((row & 7)) << 1))];
        *(float4*)(ob + (size_t)row * NSEQ + 4 * f) = v;
    }
}

// ---------------------------------------------------------------------------
// Launch
// ---------------------------------------------------------------------------
extern "C" void kernel_launch(void* const* d_in, const int* in_sizes, int n_in,
                              void* d_out, int out_size) {
    const float* q = (const float*)d_in[0];
    const float* k = (const float*)d_in[1];
    float* out = (float*)d_out;

    prep_kernel<<<(4 * BH * NSEQ) / 256, 256>>>(q, k);

    dim3 grid(NSEQ / TILE_N, NSEQ / TILE_M, BH);
    hyp_kernel<<<grid, 128>>>(out);
}